// round 7
// baseline (speedup 1.0000x reference)
#include <cuda_runtime.h>
#include <cuda_bf16.h>
#include <stdint.h>

#define BS   16
#define MM   128
#define NA   8400
#define NC   80
#define KTOP 13
#define EPS7 1e-7f
#define EPS9 1e-9f
#define FULL 0xffffffffu
#define CNT1 (1 << 20)   // packed claim increment: cnt in high bits, sum(m) low

// scratch (static device globals -- allowed)
__device__ int    g_cs  [BS * NA];    // packed: (cnt<<20) | sum_of_m
__device__ float  g_alsum[BS * NA];
__device__ float  g_ovsum[BS * NA];
__device__ unsigned long long g_best[BS * NA];
__device__ float  g_pos_am[BS * MM];
__device__ float  g_pos_ov[BS * MM];
__device__ int    g_tgt[BS * NA];
__device__ float  g_al [BS * NA];
__device__ int    g_fglist[BS * NA];
__device__ int    g_multilist[BS * NA];
__device__ int    g_nfg;
__device__ int    g_nmulti;
__device__ float4 g_gtbox[BS * MM];   // gt box
__device__ float4 g_gtaux[BS * MM];   // {at1, mask, label(int bits), unused}

// ---------------------------------------------------------------------------
// CIoU (identical math to reference _ciou + clip>=0)
// ---------------------------------------------------------------------------
__device__ __forceinline__ float ciou_core(const float4 g, const float4 p,
                                           float at_g, float at_p)
{
    const float c4pi2 = 0.40528473456935108577f;  // 4/pi^2
    float w1 = g.z - g.x, h1 = g.w - g.y + EPS7;
    float w2 = p.z - p.x, h2 = p.w - p.y + EPS7;
    float iw = fminf(g.z, p.z) - fmaxf(g.x, p.x);
    float ih = fminf(g.w, p.w) - fmaxf(g.y, p.y);
    float inter = fmaxf(iw, 0.f) * fmaxf(ih, 0.f);
    float uni = w1 * h1 + w2 * h2 - inter + EPS7;
    float iou = inter / uni;
    float cw = fmaxf(g.z, p.z) - fminf(g.x, p.x);
    float ch = fmaxf(g.w, p.w) - fminf(g.y, p.y);
    float c2 = cw * cw + ch * ch + EPS7;
    float dx = p.x + p.z - g.x - g.z;
    float dy = p.y + p.w - g.y - g.w;
    float rho2 = (dx * dx + dy * dy) * 0.25f;
    float dat = at_p - at_g;
    float v = c4pi2 * dat * dat;
    float alpha = v / (v - iou + (1.f + EPS7));
    return fmaxf(iou - (rho2 / c2 + v * alpha), 0.f);
}
__device__ __forceinline__ float ciou_hg(const float4 g, const float4 p, float at_g)
{
    return ciou_core(g, p, at_g, atanf((p.z - p.x) / (p.w - p.y + EPS7)));
}
__device__ __forceinline__ float dmin_xy(const float4 g, float ax, float ay)
{
    return fminf(fminf(ax - g.x, ay - g.y), fminf(g.z - ax, g.w - ay));
}

// ---------------------------------------------------------------------------
// K0: zero scratch + build GT prep table
// ---------------------------------------------------------------------------
__global__ __launch_bounds__(256) void k0_zero(
    const int*   __restrict__ gt_labels,
    const float* __restrict__ gt_bboxes,
    const float* __restrict__ mask_gt)
{
    int i = blockIdx.x * blockDim.x + threadIdx.x;
    if (i < BS * NA) {
        g_cs[i] = 0;
        g_alsum[i] = 0.f; g_ovsum[i] = 0.f;
        g_best[i] = 0ull;
    }
    if (i < BS * MM) {
        g_pos_am[i] = 0.f; g_pos_ov[i] = 0.f;
        float4 g = reinterpret_cast<const float4*>(gt_bboxes)[i];
        g_gtbox[i] = g;
        float4 aux;
        aux.x = atanf((g.z - g.x) / (g.w - g.y + EPS7));
        aux.y = mask_gt[i];
        aux.z = __int_as_float(gt_labels[i]);
        aux.w = 0.f;
        g_gtaux[i] = aux;
    }
    if (i == 0) { g_nfg = 0; g_nmulti = 0; }
}

// ---------------------------------------------------------------------------
// K1: one WARP per (b,m) GT row. Analytic in-gts enumeration; per-lane
// register-sorted top-13 of packed 64-bit keys (val desc, idx asc); warp
// butterfly max per selection step. Claims carry al + ov.
// ---------------------------------------------------------------------------
__global__ __launch_bounds__(256) void k1_fused(
    const float* __restrict__ pd_scores,   // [BS,NA,NC]
    const float* __restrict__ pd_bboxes,   // [BS,NA,4]
    const int*   __restrict__ gt_labels,
    const float* __restrict__ gt_bboxes,
    const float* __restrict__ mask_gt)
{
    int wid = threadIdx.x >> 5, lane = threadIdx.x & 31;
    int row = blockIdx.x * 8 + wid;        // b*MM + m
    if (row >= BS * MM) return;
    if (mask_gt[row] <= 0.f) return;       // warp-uniform
    int b = row >> 7, m = row & 127;

    float4 g = reinterpret_cast<const float4*>(gt_bboxes)[row];
    float at1 = atanf((g.z - g.x) / (g.w - g.y + EPS7));
    int lbl = gt_labels[row];
    const float*  psb = pd_scores + (size_t)b * NA * NC + lbl;
    const float4* pbb = reinterpret_cast<const float4*>(pd_bboxes) + (size_t)b * NA;

    // per-lane sorted (descending) top-13 keys: (valbits<<32)|(0x7fffffff-idx)
    unsigned long long keys[KTOP];
    #pragma unroll
    for (int j = 0; j < KTOP; ++j) keys[j] = 0ull;

    #pragma unroll
    for (int ks = 0; ks < 3; ++ks) {
        const int   n   = (ks == 0) ? 80 : (ks == 1) ? 40 : 20;
        const float s   = (ks == 0) ? 8.f : (ks == 1) ? 16.f : 32.f;
        const int   off = (ks == 0) ? 0 : (ks == 1) ? 6400 : 8000;
        int ix0 = max(0,     (int)floorf(g.x / s - 0.5f));
        int ix1 = min(n - 1, (int)floorf(g.z / s - 0.5f) + 1);
        int iy0 = max(0,     (int)floorf(g.y / s - 0.5f));
        int iy1 = min(n - 1, (int)floorf(g.w / s - 0.5f) + 1);
        int w = ix1 - ix0 + 1, h = iy1 - iy0 + 1;
        if (w <= 0 || h <= 0) continue;
        int tot = w * h;
        for (int t = lane; t < tot; t += 32) {
            int ix = ix0 + t % w, iy = iy0 + t / w;
            float ax = (ix + 0.5f) * s, ay = (iy + 0.5f) * s;
            if (dmin_xy(g, ax, ay) > EPS9) {
                int idx = off + iy * n + ix;
                float ov = ciou_hg(g, pbb[idx], at1);
                if (ov > 0.f) {
                    float sc = psb[(size_t)idx * NC];
                    float o2 = ov * ov;
                    float al = sc * (o2 * o2 * o2);
                    if (al > 0.f) {
                        unsigned long long ck =
                            ((unsigned long long)__float_as_uint(al) << 32) |
                            (unsigned)(0x7fffffff - idx);
                        if (ck > keys[KTOP - 1]) {
                            #pragma unroll
                            for (int j = 0; j < KTOP; ++j) {
                                unsigned long long kj = keys[j];
                                if (ck > kj) { keys[j] = ck; ck = kj; }
                            }
                        }
                    }
                }
            }
        }
    }

    int   mysel = -1;   // lane q holds q-th selected anchor
    float myval = 0.f;
    int qsel = 0;
    #pragma unroll 1
    for (int it = 0; it < KTOP; ++it) {
        unsigned long long k = keys[0];
        #pragma unroll
        for (int d = 16; d; d >>= 1) {
            unsigned long long o = __shfl_xor_sync(FULL, k, d);
            if (o > k) k = o;
        }
        if ((unsigned)(k >> 32) == 0u) break;   // positives exhausted
        if (lane == qsel) {
            mysel = 0x7fffffff - (int)(k & 0xffffffffu);
            myval = __uint_as_float((unsigned)(k >> 32));
        }
        qsel++;
        if (keys[0] == k) {                     // unique owner: shift down
            #pragma unroll
            for (int j = 0; j < KTOP - 1; ++j) keys[j] = keys[j + 1];
            keys[KTOP - 1] = 0ull;
        }
    }

    // claim selected positives (in-gts guaranteed); carry al + ov
    if (lane < qsel) {
        float ov = ciou_hg(g, pbb[mysel], at1);
        atomicAdd(&g_cs   [b * NA + mysel], CNT1 | m);
        atomicAdd(&g_alsum[b * NA + mysel], myval);
        atomicAdd(&g_ovsum[b * NA + mysel], ov);
    }

    // zero-fill (rare): smallest-index zero-valued anchors of the full row;
    // only in-gts ones affect the mask. al contribution is 0; add ov anyway.
    if (qsel < KTOP) {
        int sarr[KTOP];
        for (int t = 0; t < qsel; ++t)
            sarr[t] = __shfl_sync(FULL, mysel, t);
        if (lane == 0) {
            int need = KTOP - qsel;
            int j = 0;
            while (need > 0 && j < 8 * KTOP) {
                bool ispos = false;
                for (int t = 0; t < qsel; ++t) if (sarr[t] == j) { ispos = true; break; }
                if (!ispos) {
                    int ix = j % 80, iy = j / 80;   // j small -> scale-8 grid
                    float ax = (ix + 0.5f) * 8.f, ay = (iy + 0.5f) * 8.f;
                    if (dmin_xy(g, ax, ay) > EPS9) {
                        float ov = ciou_hg(g, pbb[j], at1);
                        atomicAdd(&g_cs   [b * NA + j], CNT1 | m);
                        atomicAdd(&g_ovsum[b * NA + j], ov);
                    }
                    need--;
                }
                j++;
            }
        }
    }
}

// ---------------------------------------------------------------------------
// K3a: per (b,a). cnt==0/1 fully resolved with carried sums (no math);
// cnt>1 compacted for the phase resolver.
// ---------------------------------------------------------------------------
__global__ __launch_bounds__(256) void k3a(float* __restrict__ out)
{
    int idx = blockIdx.x * blockDim.x + threadIdx.x;
    if (idx >= BS * NA) return;
    int b = idx / NA;

    int cs = g_cs[idx];
    int cnt = cs >> 20;
    if (cnt > 1) {
        int p = atomicAdd(&g_nmulti, 1);
        g_multilist[p] = idx;
        return;                            // outputs written by k3b2
    }

    int fg = cnt, tgt = 0;
    float al = 0.f;
    if (cnt == 1) {
        tgt = cs & 0xfffff;
        al  = g_alsum[idx];
        float ovm = g_ovsum[idx];
        int row = b * MM + tgt;
        atomicMax((unsigned int*)&g_pos_am[row], __float_as_uint(al));
        atomicMax((unsigned int*)&g_pos_ov[row], __float_as_uint(ovm));
        int q = atomicAdd(&g_nfg, 1);
        g_fglist[q] = idx;
    }
    g_tgt[idx] = tgt;
    g_al [idx] = al;

    int grow = b * MM + tgt;
    int lbl = max(__float_as_int(g_gtaux[grow].z), 0);
    float4 bx = g_gtbox[grow];
    float* o_lab = out;
    float* o_box = out + (size_t)BS * NA;
    float* o_fg  = out + (size_t)BS * NA * (5 + NC);
    float* o_tg  = o_fg + (size_t)BS * NA;
    o_lab[idx] = (float)lbl;
    reinterpret_cast<float4*>(o_box)[idx] = bx;
    o_fg[idx] = fg ? 1.f : 0.f;
    o_tg[idx] = (float)tgt;
}

// ---------------------------------------------------------------------------
// K3b1: one WARP per (entry, 32-m quarter): each lane one masked CIoU,
// butterfly-max packed key (val<<32 | (MM-1-m)), one atomicMax per warp.
// ---------------------------------------------------------------------------
__global__ __launch_bounds__(256) void k3b1(
    const float* __restrict__ pd_bboxes,
    const float* __restrict__ anc)
{
    int w    = (blockIdx.x * blockDim.x + threadIdx.x) >> 5;
    int nwrp = (gridDim.x * blockDim.x) >> 5;
    int lane = threadIdx.x & 31;
    int tot = g_nmulti * 4;

    for (int t = w; t < tot; t += nwrp) {
        int e = t >> 2, q = t & 3;
        int idx = g_multilist[e];
        int b = idx / NA, a = idx - b * NA;
        float4 p  = reinterpret_cast<const float4*>(pd_bboxes)[idx];
        float2 an = reinterpret_cast<const float2*>(anc)[a];
        float at2 = atanf((p.z - p.x) / (p.w - p.y + EPS7));

        int m = q * 32 + lane;
        int row = b * MM + m;
        float4 aux = g_gtaux[row];
        float v = 0.f;
        if (aux.y > 0.f) {
            float4 gg = g_gtbox[row];
            if (dmin_xy(gg, an.x, an.y) > EPS9)
                v = ciou_core(gg, p, aux.x, at2);
        }
        unsigned long long key =
            ((unsigned long long)__float_as_uint(v) << 32) |
            (unsigned)(MM - 1 - m);
        #pragma unroll
        for (int d = 16; d; d >>= 1) {
            unsigned long long o = __shfl_xor_sync(FULL, key, d);
            if (o > key) key = o;
        }
        if (lane == 0)
            atomicMax(&g_best[e], key);
    }
}

// ---------------------------------------------------------------------------
// K3b2: one thread per entry: unpack winner, assigned-pair metrics + outputs.
// ---------------------------------------------------------------------------
__global__ __launch_bounds__(256) void k3b2(
    const float* __restrict__ pd_scores,
    float* __restrict__ out)
{
    int nm = g_nmulti;
    int stride = gridDim.x * blockDim.x;
    for (int e = blockIdx.x * blockDim.x + threadIdx.x; e < nm; e += stride) {
        int idx = g_multilist[e];
        int b = idx / NA, a = idx - b * NA;
        unsigned long long k = g_best[e];
        int tgt = MM - 1 - (int)(k & 0xffffffffu);
        float ovm = __uint_as_float((unsigned)(k >> 32));
        int row = b * MM + tgt;
        int lbl = __float_as_int(g_gtaux[row].z);
        float al = 0.f;
        if (ovm > 0.f) {
            float sc = pd_scores[((size_t)b * NA + a) * NC + lbl];
            float o2 = ovm * ovm;
            al = sc * (o2 * o2 * o2);
        }
        atomicMax((unsigned int*)&g_pos_am[row], __float_as_uint(al));
        atomicMax((unsigned int*)&g_pos_ov[row], __float_as_uint(ovm));
        g_tgt[idx] = tgt;
        g_al [idx] = al;
        int qq = atomicAdd(&g_nfg, 1);
        g_fglist[qq] = idx;

        float4 bx = g_gtbox[row];
        float* o_lab = out;
        float* o_box = out + (size_t)BS * NA;
        float* o_fg  = out + (size_t)BS * NA * (5 + NC);
        float* o_tg  = o_fg + (size_t)BS * NA;
        o_lab[idx] = (float)max(lbl, 0);
        reinterpret_cast<float4*>(o_box)[idx] = bx;
        o_fg[idx] = 1.f;
        o_tg[idx] = (float)tgt;
    }
}

// ---------------------------------------------------------------------------
// K4: sparse nrm scatter over the compacted fg list (scores pre-zeroed)
// ---------------------------------------------------------------------------
__global__ __launch_bounds__(256) void k4_scatter(float* __restrict__ out)
{
    float* o_sc = out + (size_t)BS * NA * 5;
    int nfg = g_nfg;
    int stride = gridDim.x * blockDim.x;
    for (int i = blockIdx.x * blockDim.x + threadIdx.x; i < nfg; i += stride) {
        int idx = g_fglist[i];
        int b = idx / NA;
        int tgt = g_tgt[idx];
        int grow = b * MM + tgt;
        int lbl = max(__float_as_int(g_gtaux[grow].z), 0);
        float nrm = g_al[idx] * g_pos_ov[grow] / (g_pos_am[grow] + EPS9);
        o_sc[(size_t)idx * NC + lbl] = nrm;
    }
}

// ---------------------------------------------------------------------------
extern "C" void kernel_launch(void* const* d_in, const int* in_sizes, int n_in,
                              void* d_out, int out_size)
{
    const float* pd_scores = (const float*)d_in[0];
    const float* pd_bboxes = (const float*)d_in[1];
    const float* anc       = (const float*)d_in[2];
    const int*   gt_labels = (const int*)  d_in[3];
    const float* gt_bboxes = (const float*)d_in[4];
    const float* mask_gt   = (const float*)d_in[5];
    float* out = (float*)d_out;

    // side stream for the big output-zeroing memset (fork/join in the graph)
    static cudaStream_t s2 = nullptr;
    static cudaEvent_t evFork = nullptr, evJoin = nullptr;
    if (!s2) {
        cudaStreamCreateWithFlags(&s2, cudaStreamNonBlocking);
        cudaEventCreateWithFlags(&evFork, cudaEventDisableTiming);
        cudaEventCreateWithFlags(&evJoin, cudaEventDisableTiming);
    }

    float* o_sc = out + (size_t)BS * NA * 5;

    cudaEventRecord(evFork, 0);
    cudaStreamWaitEvent(s2, evFork, 0);
    cudaMemsetAsync(o_sc, 0, (size_t)BS * NA * NC * sizeof(float), s2);
    cudaEventRecord(evJoin, s2);

    int n = BS * NA;
    k0_zero<<<(n + 255) / 256, 256>>>(gt_labels, gt_bboxes, mask_gt);
    k1_fused<<<(BS * MM + 7) / 8, 256>>>(pd_scores, pd_bboxes,
                                         gt_labels, gt_bboxes, mask_gt);
    k3a<<<(n + 255) / 256, 256>>>(out);
    k3b1<<<1024, 256>>>(pd_bboxes, anc);
    k3b2<<<64, 256>>>(pd_scores, out);

    cudaStreamWaitEvent(0, evJoin, 0);     // memset must finish before scatter
    k4_scatter<<<64, 256>>>(out);
}

// round 8
// speedup vs baseline: 1.1604x; 1.1604x over previous
#include <cuda_runtime.h>
#include <cuda_bf16.h>
#include <stdint.h>

#define BS   16
#define MM   128
#define NA   8400
#define NC   80
#define KTOP 13
#define CAP  1024
#define EPS7 1e-7f
#define EPS9 1e-9f
#define FULL 0xffffffffu
#define CNT1 (1 << 20)   // packed claim increment: cnt in high bits, sum(m) low

// scratch (static device globals -- allowed)
__device__ int    g_cs  [BS * NA];    // packed: (cnt<<20) | sum_of_m
__device__ float  g_alsum[BS * NA];
__device__ float  g_ovsum[BS * NA];
__device__ unsigned long long g_best[BS * NA];
__device__ unsigned long long g_cand[(size_t)BS * MM * CAP];
__device__ int    g_ccount[BS * MM];
__device__ float  g_pos_am[BS * MM];
__device__ float  g_pos_ov[BS * MM];
__device__ int    g_tgt[BS * NA];
__device__ float  g_al [BS * NA];
__device__ int    g_fglist[BS * NA];
__device__ int    g_multilist[BS * NA];
__device__ int    g_nfg;
__device__ int    g_nmulti;
__device__ float4 g_gtbox[BS * MM];   // gt box
__device__ float4 g_gtaux[BS * MM];   // {at1, mask, label(int bits), unused}

// ---------------------------------------------------------------------------
// CIoU (identical math to reference _ciou + clip>=0)
// ---------------------------------------------------------------------------
__device__ __forceinline__ float ciou_core(const float4 g, const float4 p,
                                           float at_g, float at_p)
{
    const float c4pi2 = 0.40528473456935108577f;  // 4/pi^2
    float w1 = g.z - g.x, h1 = g.w - g.y + EPS7;
    float w2 = p.z - p.x, h2 = p.w - p.y + EPS7;
    float iw = fminf(g.z, p.z) - fmaxf(g.x, p.x);
    float ih = fminf(g.w, p.w) - fmaxf(g.y, p.y);
    float inter = fmaxf(iw, 0.f) * fmaxf(ih, 0.f);
    float uni = w1 * h1 + w2 * h2 - inter + EPS7;
    float iou = inter / uni;
    float cw = fmaxf(g.z, p.z) - fminf(g.x, p.x);
    float ch = fmaxf(g.w, p.w) - fminf(g.y, p.y);
    float c2 = cw * cw + ch * ch + EPS7;
    float dx = p.x + p.z - g.x - g.z;
    float dy = p.y + p.w - g.y - g.w;
    float rho2 = (dx * dx + dy * dy) * 0.25f;
    float dat = at_p - at_g;
    float v = c4pi2 * dat * dat;
    float alpha = v / (v - iou + (1.f + EPS7));
    return fmaxf(iou - (rho2 / c2 + v * alpha), 0.f);
}
__device__ __forceinline__ float ciou_hg(const float4 g, const float4 p, float at_g)
{
    return ciou_core(g, p, at_g, atanf((p.z - p.x) / (p.w - p.y + EPS7)));
}
__device__ __forceinline__ float dmin_xy(const float4 g, float ax, float ay)
{
    return fminf(fminf(ax - g.x, ay - g.y), fminf(g.z - ax, g.w - ay));
}

// ---------------------------------------------------------------------------
// K0: zero scratch + build GT prep table
// ---------------------------------------------------------------------------
__global__ __launch_bounds__(256) void k0_zero(
    const int*   __restrict__ gt_labels,
    const float* __restrict__ gt_bboxes,
    const float* __restrict__ mask_gt)
{
    int i = blockIdx.x * blockDim.x + threadIdx.x;
    if (i < BS * NA) {
        g_cs[i] = 0;
        g_alsum[i] = 0.f; g_ovsum[i] = 0.f;
    }
    if (i < BS * MM) {
        g_ccount[i] = 0;
        g_pos_am[i] = 0.f; g_pos_ov[i] = 0.f;
        float4 g = reinterpret_cast<const float4*>(gt_bboxes)[i];
        g_gtbox[i] = g;
        float4 aux;
        aux.x = atanf((g.z - g.x) / (g.w - g.y + EPS7));
        aux.y = mask_gt[i];
        aux.z = __int_as_float(gt_labels[i]);
        aux.w = 0.f;
        g_gtaux[i] = aux;
    }
    if (i == 0) { g_nfg = 0; g_nmulti = 0; }
}

// ---------------------------------------------------------------------------
// K1a: one THREAD per (row, rect-cell). Computes align metric; positives
// are pushed into the per-row candidate buffer as packed keys.
// ---------------------------------------------------------------------------
__global__ __launch_bounds__(256) void k1a(
    const float* __restrict__ pd_scores,
    const float* __restrict__ pd_bboxes,
    const int*   __restrict__ gt_labels,
    const float* __restrict__ gt_bboxes,
    const float* __restrict__ mask_gt)
{
    int row = blockIdx.y;                  // b*MM + m
    if (mask_gt[row] <= 0.f) return;
    int t = blockIdx.x * 256 + threadIdx.x;

    float4 g = reinterpret_cast<const float4*>(gt_bboxes)[row];

    // rect ranges on 3 scales
    int ix0s[3], iy0s[3], ws[3], hs[3];
    int tot = 0, t0 = 0, t1 = 0;
    #pragma unroll
    for (int ks = 0; ks < 3; ++ks) {
        const int   n = (ks == 0) ? 80 : (ks == 1) ? 40 : 20;
        const float s = (ks == 0) ? 8.f : (ks == 1) ? 16.f : 32.f;
        int ix0 = max(0,     (int)floorf(g.x / s - 0.5f));
        int ix1 = min(n - 1, (int)floorf(g.z / s - 0.5f) + 1);
        int iy0 = max(0,     (int)floorf(g.y / s - 0.5f));
        int iy1 = min(n - 1, (int)floorf(g.w / s - 0.5f) + 1);
        int w = max(ix1 - ix0 + 1, 0), h = max(iy1 - iy0 + 1, 0);
        ix0s[ks] = ix0; iy0s[ks] = iy0; ws[ks] = w; hs[ks] = h;
        if (ks == 0) t0 = w * h;
        if (ks == 1) t1 = w * h;
        tot += w * h;
    }
    if (t >= tot) return;

    int ks, tc;
    if (t < t0)            { ks = 0; tc = t; }
    else if (t < t0 + t1)  { ks = 1; tc = t - t0; }
    else                   { ks = 2; tc = t - t0 - t1; }
    const int   n   = (ks == 0) ? 80 : (ks == 1) ? 40 : 20;
    const float s   = (ks == 0) ? 8.f : (ks == 1) ? 16.f : 32.f;
    const int   off = (ks == 0) ? 0 : (ks == 1) ? 6400 : 8000;
    int ix = ix0s[ks] + tc % ws[ks];
    int iy = iy0s[ks] + tc / ws[ks];
    float ax = (ix + 0.5f) * s, ay = (iy + 0.5f) * s;
    if (dmin_xy(g, ax, ay) <= EPS9) return;

    int b = row >> 7;
    int idx = off + iy * n + ix;
    float at1 = atanf((g.z - g.x) / (g.w - g.y + EPS7));
    float4 p = reinterpret_cast<const float4*>(pd_bboxes)[(size_t)b * NA + idx];
    float ov = ciou_hg(g, p, at1);
    if (ov <= 0.f) return;
    int lbl = gt_labels[row];
    float sc = pd_scores[((size_t)b * NA + idx) * NC + lbl];
    float o2 = ov * ov;
    float al = sc * (o2 * o2 * o2);
    if (al <= 0.f) return;

    int slot = atomicAdd(&g_ccount[row], 1);
    if (slot < CAP)
        g_cand[(size_t)row * CAP + slot] =
            ((unsigned long long)__float_as_uint(al) << 32) |
            (unsigned)(0x7fffffff - idx);
}

// ---------------------------------------------------------------------------
// K1b: one WARP per row: top-13 selection over candidate keys (jax
// tie-break: value desc, index asc), claims carry al + ov.
// ---------------------------------------------------------------------------
__global__ __launch_bounds__(256) void k1b(
    const float* __restrict__ pd_bboxes,
    const float* __restrict__ gt_bboxes,
    const float* __restrict__ mask_gt)
{
    int wid = threadIdx.x >> 5, lane = threadIdx.x & 31;
    int row = blockIdx.x * 8 + wid;
    if (row >= BS * MM) return;
    if (mask_gt[row] <= 0.f) return;
    int b = row >> 7, m = row & 127;

    int ncand = min(g_ccount[row], CAP);
    const unsigned long long* cp = g_cand + (size_t)row * CAP;

    unsigned long long keys[KTOP];
    #pragma unroll
    for (int j = 0; j < KTOP; ++j) keys[j] = 0ull;

    for (int j = lane; j < ncand; j += 32) {
        unsigned long long ck = cp[j];
        if (ck > keys[KTOP - 1]) {
            #pragma unroll
            for (int q = 0; q < KTOP; ++q) {
                unsigned long long kq = keys[q];
                if (ck > kq) { keys[q] = ck; ck = kq; }
            }
        }
    }

    int   mysel = -1;
    float myval = 0.f;
    int qsel = 0;
    #pragma unroll 1
    for (int it = 0; it < KTOP; ++it) {
        unsigned long long k = keys[0];
        #pragma unroll
        for (int d = 16; d; d >>= 1) {
            unsigned long long o = __shfl_xor_sync(FULL, k, d);
            if (o > k) k = o;
        }
        if ((unsigned)(k >> 32) == 0u) break;
        if (lane == qsel) {
            mysel = 0x7fffffff - (int)(k & 0xffffffffu);
            myval = __uint_as_float((unsigned)(k >> 32));
        }
        qsel++;
        if (keys[0] == k) {
            #pragma unroll
            for (int j = 0; j < KTOP - 1; ++j) keys[j] = keys[j + 1];
            keys[KTOP - 1] = 0ull;
        }
    }

    float4 g = reinterpret_cast<const float4*>(gt_bboxes)[row];

    // claim selected positives (in-gts guaranteed); carry al + ov
    if (lane < qsel) {
        float at1 = atanf((g.z - g.x) / (g.w - g.y + EPS7));
        float4 p = reinterpret_cast<const float4*>(pd_bboxes)[(size_t)b * NA + mysel];
        float ov = ciou_hg(g, p, at1);
        atomicAdd(&g_cs   [b * NA + mysel], CNT1 | m);
        atomicAdd(&g_alsum[b * NA + mysel], myval);
        atomicAdd(&g_ovsum[b * NA + mysel], ov);
    }

    // zero-fill (rare): smallest-index zero-valued anchors of the full row;
    // only in-gts ones affect the mask. al contribution is 0; add ov anyway.
    if (qsel < KTOP) {
        int sarr[KTOP];
        for (int t = 0; t < qsel; ++t)
            sarr[t] = __shfl_sync(FULL, mysel, t);
        if (lane == 0) {
            float at1 = atanf((g.z - g.x) / (g.w - g.y + EPS7));
            const float4* pbb = reinterpret_cast<const float4*>(pd_bboxes) + (size_t)b * NA;
            int need = KTOP - qsel;
            int j = 0;
            while (need > 0 && j < 8 * KTOP) {
                bool ispos = false;
                for (int t = 0; t < qsel; ++t) if (sarr[t] == j) { ispos = true; break; }
                if (!ispos) {
                    int ix = j % 80, iy = j / 80;   // j small -> scale-8 grid
                    float ax = (ix + 0.5f) * 8.f, ay = (iy + 0.5f) * 8.f;
                    if (dmin_xy(g, ax, ay) > EPS9) {
                        float ov = ciou_hg(g, pbb[j], at1);
                        atomicAdd(&g_cs   [b * NA + j], CNT1 | m);
                        atomicAdd(&g_ovsum[b * NA + j], ov);
                    }
                    need--;
                }
                j++;
            }
        }
    }
}

// ---------------------------------------------------------------------------
// K3a: per (b,a). cnt==0/1 fully resolved with carried sums (no math);
// cnt>1 compacted (g_best seeded to key(v=0, m=0)).
// ---------------------------------------------------------------------------
__global__ __launch_bounds__(256) void k3a(float* __restrict__ out)
{
    int idx = blockIdx.x * blockDim.x + threadIdx.x;
    if (idx >= BS * NA) return;
    int b = idx / NA;

    int cs = g_cs[idx];
    int cnt = cs >> 20;
    if (cnt > 1) {
        int p = atomicAdd(&g_nmulti, 1);
        g_multilist[p] = idx;
        g_best[p] = (unsigned long long)(MM - 1);   // v=0, m=0 default
        return;                            // outputs written by k3b2
    }

    int fg = cnt, tgt = 0;
    float al = 0.f;
    if (cnt == 1) {
        tgt = cs & 0xfffff;
        al  = g_alsum[idx];
        float ovm = g_ovsum[idx];
        int row = b * MM + tgt;
        atomicMax((unsigned int*)&g_pos_am[row], __float_as_uint(al));
        atomicMax((unsigned int*)&g_pos_ov[row], __float_as_uint(ovm));
        int q = atomicAdd(&g_nfg, 1);
        g_fglist[q] = idx;
    }
    g_tgt[idx] = tgt;
    g_al [idx] = al;

    int grow = b * MM + tgt;
    int lbl = max(__float_as_int(g_gtaux[grow].z), 0);
    float4 bx = g_gtbox[grow];
    float* o_lab = out;
    float* o_box = out + (size_t)BS * NA;
    float* o_fg  = out + (size_t)BS * NA * (5 + NC);
    float* o_tg  = o_fg + (size_t)BS * NA;
    o_lab[idx] = (float)lbl;
    reinterpret_cast<float4*>(o_box)[idx] = bx;
    o_fg[idx] = fg ? 1.f : 0.f;
    o_tg[idx] = (float)tgt;
}

// ---------------------------------------------------------------------------
// K3b1: one THREAD per (entry, m): masked CIoU; atomicMax packed key
// (val<<32 | (MM-1-m)) only when v>0 (~4 contenders per entry).
// ---------------------------------------------------------------------------
__global__ __launch_bounds__(256) void k3b1(
    const float* __restrict__ pd_bboxes,
    const float* __restrict__ anc)
{
    int tot = g_nmulti * MM;
    int stride = gridDim.x * blockDim.x;
    for (int t = blockIdx.x * blockDim.x + threadIdx.x; t < tot; t += stride) {
        int e = t >> 7, m = t & 127;
        int idx = g_multilist[e];
        int b = idx / NA, a = idx - b * NA;
        int row = b * MM + m;
        float4 aux = g_gtaux[row];
        if (aux.y <= 0.f) continue;
        float2 an = reinterpret_cast<const float2*>(anc)[a];
        float4 gg = g_gtbox[row];
        if (dmin_xy(gg, an.x, an.y) <= EPS9) continue;
        float4 p = reinterpret_cast<const float4*>(pd_bboxes)[idx];
        float at2 = atanf((p.z - p.x) / (p.w - p.y + EPS7));
        float v = ciou_core(gg, p, aux.x, at2);
        if (v > 0.f) {
            unsigned long long key =
                ((unsigned long long)__float_as_uint(v) << 32) |
                (unsigned)(MM - 1 - m);
            atomicMax(&g_best[e], key);
        }
    }
}

// ---------------------------------------------------------------------------
// K3b2: one thread per entry: unpack winner, assigned-pair metrics + outputs.
// ---------------------------------------------------------------------------
__global__ __launch_bounds__(256) void k3b2(
    const float* __restrict__ pd_scores,
    float* __restrict__ out)
{
    int nm = g_nmulti;
    int stride = gridDim.x * blockDim.x;
    for (int e = blockIdx.x * blockDim.x + threadIdx.x; e < nm; e += stride) {
        int idx = g_multilist[e];
        int b = idx / NA, a = idx - b * NA;
        unsigned long long k = g_best[e];
        int tgt = MM - 1 - (int)(k & 0xffffffffu);
        float ovm = __uint_as_float((unsigned)(k >> 32));
        int row = b * MM + tgt;
        int lbl = __float_as_int(g_gtaux[row].z);
        float al = 0.f;
        if (ovm > 0.f) {
            float sc = pd_scores[((size_t)b * NA + a) * NC + lbl];
            float o2 = ovm * ovm;
            al = sc * (o2 * o2 * o2);
        }
        atomicMax((unsigned int*)&g_pos_am[row], __float_as_uint(al));
        atomicMax((unsigned int*)&g_pos_ov[row], __float_as_uint(ovm));
        g_tgt[idx] = tgt;
        g_al [idx] = al;
        int qq = atomicAdd(&g_nfg, 1);
        g_fglist[qq] = idx;

        float4 bx = g_gtbox[row];
        float* o_lab = out;
        float* o_box = out + (size_t)BS * NA;
        float* o_fg  = out + (size_t)BS * NA * (5 + NC);
        float* o_tg  = o_fg + (size_t)BS * NA;
        o_lab[idx] = (float)max(lbl, 0);
        reinterpret_cast<float4*>(o_box)[idx] = bx;
        o_fg[idx] = 1.f;
        o_tg[idx] = (float)tgt;
    }
}

// ---------------------------------------------------------------------------
// K4: sparse nrm scatter over the compacted fg list (scores pre-zeroed)
// ---------------------------------------------------------------------------
__global__ __launch_bounds__(256) void k4_scatter(float* __restrict__ out)
{
    float* o_sc = out + (size_t)BS * NA * 5;
    int nfg = g_nfg;
    int stride = gridDim.x * blockDim.x;
    for (int i = blockIdx.x * blockDim.x + threadIdx.x; i < nfg; i += stride) {
        int idx = g_fglist[i];
        int b = idx / NA;
        int tgt = g_tgt[idx];
        int grow = b * MM + tgt;
        int lbl = max(__float_as_int(g_gtaux[grow].z), 0);
        float nrm = g_al[idx] * g_pos_ov[grow] / (g_pos_am[grow] + EPS9);
        o_sc[(size_t)idx * NC + lbl] = nrm;
    }
}

// ---------------------------------------------------------------------------
extern "C" void kernel_launch(void* const* d_in, const int* in_sizes, int n_in,
                              void* d_out, int out_size)
{
    const float* pd_scores = (const float*)d_in[0];
    const float* pd_bboxes = (const float*)d_in[1];
    const float* anc       = (const float*)d_in[2];
    const int*   gt_labels = (const int*)  d_in[3];
    const float* gt_bboxes = (const float*)d_in[4];
    const float* mask_gt   = (const float*)d_in[5];
    float* out = (float*)d_out;

    // side stream for the big output-zeroing memset (fork/join in the graph)
    static cudaStream_t s2 = nullptr;
    static cudaEvent_t evFork = nullptr, evJoin = nullptr;
    if (!s2) {
        cudaStreamCreateWithFlags(&s2, cudaStreamNonBlocking);
        cudaEventCreateWithFlags(&evFork, cudaEventDisableTiming);
        cudaEventCreateWithFlags(&evJoin, cudaEventDisableTiming);
    }

    float* o_sc = out + (size_t)BS * NA * 5;
    cudaEventRecord(evFork, 0);
    cudaStreamWaitEvent(s2, evFork, 0);
    cudaMemsetAsync(o_sc, 0, (size_t)BS * NA * NC * sizeof(float), s2);
    cudaEventRecord(evJoin, s2);

    int n = BS * NA;
    k0_zero<<<(n + 255) / 256, 256>>>(gt_labels, gt_bboxes, mask_gt);
    k1a<<<dim3(5, BS * MM), 256>>>(pd_scores, pd_bboxes,
                                   gt_labels, gt_bboxes, mask_gt);
    k1b<<<(BS * MM + 7) / 8, 256>>>(pd_bboxes, gt_bboxes, mask_gt);
    k3a<<<(n + 255) / 256, 256>>>(out);
    k3b1<<<2048, 256>>>(pd_bboxes, anc);
    k3b2<<<64, 256>>>(pd_scores, out);

    cudaStreamWaitEvent(0, evJoin, 0);     // memset must finish before scatter
    k4_scatter<<<64, 256>>>(out);
}